// round 6
// baseline (speedup 1.0000x reference)
#include <cuda_runtime.h>

#define TPB  512
#define ROWS 64
#define XSTR 146   // activation row stride — EVEN: 8B alignment for f32x2/float2 ops
#define SSTR 51    // state tile row stride

typedef unsigned long long ull;

// ---- embedding-region offsets inside smem (floats) ----
enum {
  EO_SUIT = 0,        // 5  x 8
  EO_RANK = 40,       // 14 x 8
  EO_POS = 152,       // 7  x 8
  EO_ACTION = 208,    // 12 x 8
  EO_ACTIVE = 304,    // 2  x 8
  EO_STREET = 320,    // 5  x 8
  EO_NUMP = 360,      // 7  x 8
  EO_BLIND = 416,     // 2  x 8
  EO_SW = 432,        // 6  x 8 scalar_W
  EO_SB = 480,        // 6  x 8 scalar_b
  EO_TOTAL = 528
};

__constant__ int c_seg_base[31] = {
  EO_STREET, EO_POS,
  EO_ACTIVE, EO_ACTIVE, EO_ACTIVE, EO_ACTIVE, EO_ACTIVE,
  EO_POS, EO_POS, EO_POS, EO_POS, EO_POS,
  -1, -3, -4, -6,
  EO_POS, EO_ACTION, EO_BLIND,
  -2,
  EO_ACTION, EO_POS, EO_BLIND,
  EO_NUMP, EO_POS,
  -5, -5, -5, -5, -5, -5
};
__constant__ int c_seg_col[31] = {
  18, 20,
  22, 23, 24, 25, 26,
  27, 28, 29, 30, 31,
  40, 41, 42, 43,
  35, 36, 37,
  39,
  32, 33, 34,
  19, 38,
  44, 45, 46, 47, 48, 49
};

struct Params {
  const float* state;
  const float* suit_emb; const float* rank_emb;
  const float *hW1, *hb1, *hW2, *hb2, *hW3, *hb3;
  const float *bW1, *bb1, *bW2, *bb2, *bW3, *bb3;
  const float *cW1, *cb1, *cW2, *cb2, *cW3, *cb3;
  const float *pos_emb, *action_emb, *active_emb, *street_emb, *nump_emb, *blind_emb;
  const float *scalar_W, *scalar_b;
  float* out;
  int nrows;
};

#define CP_COMMIT() asm volatile("cp.async.commit_group;" ::: "memory")
#define CP_WAIT0()  asm volatile("cp.async.wait_group 0;"  ::: "memory")

__device__ __forceinline__ void cp_f(float* dst, const float* __restrict__ src, int n, int tid) {
  for (int e = tid; e < n; e += TPB) dst[e] = src[e];
}

// Async-stage W[rows, cols] into smem as [rows, padcols] (zero pad), 16B chunks.
__device__ __forceinline__ void stageW(float* dW, const float* __restrict__ W,
                                       int rows, int cols, int padcols, int tid)
{
  const int rc4 = padcols >> 2;
  const int total = rows * rc4;
  unsigned dbase = (unsigned)__cvta_generic_to_shared(dW);
  for (int e = tid; e < total; e += TPB) {
    int r = e / rc4, c4 = e - r * rc4;
    if ((c4 << 2) < cols) {
      const float4* src = reinterpret_cast<const float4*>(W + (size_t)r * cols) + c4;
      unsigned d = dbase + (unsigned)(e << 4);
      asm volatile("cp.async.cg.shared.global [%0], [%1], 16;" :: "r"(d), "l"(src) : "memory");
    } else {
      reinterpret_cast<float4*>(dW)[e] = make_float4(0.f, 0.f, 0.f, 0.f);
    }
  }
}
__device__ __forceinline__ void stageB(float* dB, const float* __restrict__ b,
                                       int cols, int padcols, int tid)
{
  const int total = padcols >> 2;
  unsigned dbase = (unsigned)__cvta_generic_to_shared(dB);
  for (int e = tid; e < total; e += TPB) {
    if ((e << 2) < cols) {
      unsigned d = dbase + (unsigned)(e << 4);
      asm volatile("cp.async.cg.shared.global [%0], [%1], 16;"
                   :: "r"(d), "l"(reinterpret_cast<const float4*>(b) + e) : "memory");
    } else {
      reinterpret_cast<float4*>(dB)[e] = make_float4(0.f, 0.f, 0.f, 0.f);
    }
  }
}

// Y[64, NS] = X[64, K] @ W[K, NS] + b  (store first NSTORE cols), optional leaky.
// 512 threads = 8 colblocks (CB cols) x 64 rows (1 row/thread).
// Inner product uses packed fma.rn.f32x2 (SASS FFMA2) -> 2 MACs/inst.
template<int K, int NS, int NSTORE, int CB, bool LEAKY>
__device__ __forceinline__ void gemm_tile(const float* __restrict__ Xs, float* __restrict__ Ys,
                                          const float* __restrict__ Ws, const float* __restrict__ Bs,
                                          int tid)
{
  constexpr int NP = CB / 2;
  const int cb = tid & 7;
  const int r  = tid >> 3;            // 0..63

  ull acc[NP];
  const ull* bp = reinterpret_cast<const ull*>(Bs + cb * CB);
#pragma unroll
  for (int j = 0; j < NP; ++j) acc[j] = bp[j];   // start from packed bias

  const float* xr = Xs + r * XSTR;
  constexpr int UNR = (CB >= 16) ? 2 : 4;
#pragma unroll (UNR)
  for (int k = 0; k < K; ++k) {
    const ull* wp = reinterpret_cast<const ull*>(Ws + k * NS + cb * CB);
    float x = xr[k];
    ull xx; asm("mov.b64 %0, {%1, %1};" : "=l"(xx) : "f"(x));
#pragma unroll
    for (int j = 0; j < NP; ++j) {
      ull w = wp[j];
      asm("fma.rn.f32x2 %0, %1, %2, %3;" : "=l"(acc[j]) : "l"(w), "l"(xx), "l"(acc[j]));
    }
  }

  float* yr = Ys + r * XSTR;
#pragma unroll
  for (int j = 0; j < NP; ++j) {
    float lo, hi;
    asm("mov.b64 {%0, %1}, %2;" : "=f"(lo), "=f"(hi) : "l"(acc[j]));
    if (LEAKY) { lo = fmaxf(lo, 0.01f * lo); hi = fmaxf(hi, 0.01f * hi); }
    int col = cb * CB + 2 * j;
    if (col < NSTORE) *reinterpret_cast<float2*>(yr + col) = make_float2(lo, hi);
  }
}

__global__ void __launch_bounds__(TPB, 1)
PreProcess_kernel(Params p)
{
  extern __shared__ float sm[];
  float* stateS = sm;                       // 64*51   = 3264
  float* X      = stateS + ROWS * SSTR;     // 64*146  = 9344
  float* Y      = X + ROWS * XSTR;          // 9344
  float* WA     = Y + ROWS * XSTR;          // 144*160 = 23040
  float* BA     = WA + 144 * 160;           // 160
  float* WB     = BA + 160;                 // 144*64  = 9216
  float* BB     = WB + 144 * 64;            // 96
  float* embS   = BB + 96;                  // 528

  const int tid  = threadIdx.x;
  const int row0 = blockIdx.x * ROWS;

  // ---- prefetch first weights, stage state tile + small tables ----
  stageW(WA, p.hW1, 64, 64, 64, tid);
  stageB(BA, p.hb1, 64, 64, tid);
  CP_COMMIT();

  for (int e = tid; e < ROWS * 50; e += TPB) {
    int r = e / 50, c = e - r * 50;
    float v = 0.f;
    if (row0 + r < p.nrows) v = p.state[(size_t)(row0 + r) * 50 + c];
    stateS[r * SSTR + c] = v;
  }
  cp_f(embS + EO_SUIT,   p.suit_emb,   40, tid);
  cp_f(embS + EO_RANK,   p.rank_emb,  112, tid);
  cp_f(embS + EO_POS,    p.pos_emb,    56, tid);
  cp_f(embS + EO_ACTION, p.action_emb, 96, tid);
  cp_f(embS + EO_ACTIVE, p.active_emb, 16, tid);
  cp_f(embS + EO_STREET, p.street_emb, 40, tid);
  cp_f(embS + EO_NUMP,   p.nump_emb,   56, tid);
  cp_f(embS + EO_BLIND,  p.blind_emb,  16, tid);
  cp_f(embS + EO_SW,     p.scalar_W,   48, tid);
  cp_f(embS + EO_SB,     p.scalar_b,   48, tid);
  CP_WAIT0();
  __syncthreads();

  // ---- build card inputs: X[:,0:64]=hand, X[:,64:144]=board ----
  for (int e = tid; e < ROWS * 144; e += TPB) {
    int r = e / 144, c = e - r * 144;
    int card = c >> 4, t = c & 15;
    float v;
    if (t < 8) {
      int s = (int)stateS[r * SSTR + 2 * card + 1];
      v = embS[EO_SUIT + s * 8 + t];
    } else {
      int rk = (int)stateS[r * SSTR + 2 * card];
      v = embS[EO_RANK + rk * 8 + (t - 8)];
    }
    X[r * XSTR + c] = v;
  }
  __syncthreads();

  // ---- pipelined layers: prefetch next weights (cp.async) during current gemm ----
  stageW(WB, p.bW1, 80, 80, 96, tid); stageB(BB, p.bb1, 80, 96, tid); CP_COMMIT();
  gemm_tile<64, 64, 64, 8, true >(X, Y, WA, BA, tid);
  CP_WAIT0(); __syncthreads();

  stageW(WA, p.hW2, 64, 64, 64, tid); stageB(BA, p.hb2, 64, 64, tid); CP_COMMIT();
  gemm_tile<80, 96, 80, 12, true >(X + 64, Y + 64, WB, BB, tid);
  CP_WAIT0(); __syncthreads();

  stageW(WB, p.bW2, 80, 80, 96, tid); stageB(BB, p.bb2, 80, 96, tid); CP_COMMIT();
  gemm_tile<64, 64, 64, 8, true >(Y, X, WA, BA, tid);
  CP_WAIT0(); __syncthreads();

  stageW(WA, p.hW3, 64, 64, 64, tid); stageB(BA, p.hb3, 64, 64, tid); CP_COMMIT();
  gemm_tile<80, 96, 80, 12, true >(Y + 64, X + 64, WB, BB, tid);
  CP_WAIT0(); __syncthreads();

  stageW(WB, p.bW3, 80, 80, 96, tid); stageB(BB, p.bb3, 80, 96, tid); CP_COMMIT();
  gemm_tile<64, 64, 64, 8, false>(X, Y, WA, BA, tid);
  CP_WAIT0(); __syncthreads();

  stageW(WA, p.cW1, 144, 144, 160, tid); stageB(BA, p.cb1, 144, 160, tid); CP_COMMIT();
  gemm_tile<80, 96, 80, 12, false>(X + 64, Y + 64, WB, BB, tid);
  CP_WAIT0(); __syncthreads();

  stageW(WB, p.cW2, 144, 64, 64, tid); stageB(BB, p.cb2, 64, 64, tid); CP_COMMIT();
  gemm_tile<144, 160, 144, 20, true >(Y, X, WA, BA, tid);   // hb layer 1 (concat = Y[:,0:144])
  CP_WAIT0(); __syncthreads();

  stageW(WA, p.cW3, 64, 64, 64, tid); stageB(BA, p.cb3, 64, 64, tid); CP_COMMIT();
  gemm_tile<144, 64, 64, 8, true >(X, Y, WB, BB, tid);
  CP_WAIT0(); __syncthreads();

  gemm_tile<64, 64, 64, 8, false>(Y, X, WA, BA, tid);
  __syncthreads();
  // final hand_board in X[:,0:64]

  // ---- assemble 312-float output rows (coalesced) ----
  size_t obase = (size_t)row0 * 312;
  for (int e = tid; e < ROWS * 312; e += TPB) {
    int r = e / 312, c = e - r * 312;
    if (row0 + r >= p.nrows) continue;
    float v;
    if (c < 64) {
      v = X[r * XSTR + c];
    } else {
      int s = (c - 64) >> 3, j = (c - 64) & 7;
      int base = c_seg_base[s];
      float sv = stateS[r * SSTR + c_seg_col[s]];
      if (base >= 0) {
        int idx = (int)sv;
        v = embS[base + idx * 8 + j];
      } else {
        int w = -base - 1;
        v = fmaf(sv, embS[EO_SW + w * 8 + j], embS[EO_SB + w * 8 + j]);
      }
    }
    p.out[obase + e] = v;
  }
}

extern "C" void kernel_launch(void* const* d_in, const int* in_sizes, int n_in,
                              void* d_out, int out_size)
{
  Params p;
  p.state      = (const float*)d_in[0];
  p.suit_emb   = (const float*)d_in[1];
  p.rank_emb   = (const float*)d_in[2];
  p.hW1 = (const float*)d_in[3];  p.hb1 = (const float*)d_in[4];
  p.hW2 = (const float*)d_in[5];  p.hb2 = (const float*)d_in[6];
  p.hW3 = (const float*)d_in[7];  p.hb3 = (const float*)d_in[8];
  p.bW1 = (const float*)d_in[9];  p.bb1 = (const float*)d_in[10];
  p.bW2 = (const float*)d_in[11]; p.bb2 = (const float*)d_in[12];
  p.bW3 = (const float*)d_in[13]; p.bb3 = (const float*)d_in[14];
  p.cW1 = (const float*)d_in[15]; p.cb1 = (const float*)d_in[16];
  p.cW2 = (const float*)d_in[17]; p.cb2 = (const float*)d_in[18];
  p.cW3 = (const float*)d_in[19]; p.cb3 = (const float*)d_in[20];
  p.pos_emb    = (const float*)d_in[21];
  p.action_emb = (const float*)d_in[22];
  p.active_emb = (const float*)d_in[23];
  p.street_emb = (const float*)d_in[24];
  p.nump_emb   = (const float*)d_in[25];
  p.blind_emb  = (const float*)d_in[26];
  p.scalar_W   = (const float*)d_in[27];
  p.scalar_b   = (const float*)d_in[28];
  p.out   = (float*)d_out;
  p.nrows = in_sizes[0] / 50;

  const int smem_floats = ROWS * SSTR + 2 * ROWS * XSTR
                        + 144 * 160 + 160 + 144 * 64 + 96 + EO_TOTAL;
  const int smem_bytes = smem_floats * (int)sizeof(float);
  cudaFuncSetAttribute(PreProcess_kernel,
                       cudaFuncAttributeMaxDynamicSharedMemorySize, smem_bytes);

  int grid = (p.nrows + ROWS - 1) / ROWS;
  PreProcess_kernel<<<grid, TPB, smem_bytes>>>(p);
}

// round 7
// speedup vs baseline: 1.9546x; 1.9546x over previous
#include <cuda_runtime.h>

#define TPB  256
#define ROWS 64
#define XSTR 146   // even (8B-aligned k-pairs); 146 mod 32 = 18 -> distinct banks across rowgroups
#define SSTR 51

typedef unsigned long long ull;

// ---- embedding-region offsets inside smem (floats) ----
enum {
  EO_SUIT = 0, EO_RANK = 40, EO_POS = 152, EO_ACTION = 208, EO_ACTIVE = 304,
  EO_STREET = 320, EO_NUMP = 360, EO_BLIND = 416, EO_SW = 432, EO_SB = 480,
  EO_TOTAL = 528
};

__constant__ int c_seg_base[31] = {
  EO_STREET, EO_POS,
  EO_ACTIVE, EO_ACTIVE, EO_ACTIVE, EO_ACTIVE, EO_ACTIVE,
  EO_POS, EO_POS, EO_POS, EO_POS, EO_POS,
  -1, -3, -4, -6,
  EO_POS, EO_ACTION, EO_BLIND,
  -2,
  EO_ACTION, EO_POS, EO_BLIND,
  EO_NUMP, EO_POS,
  -5, -5, -5, -5, -5, -5
};
__constant__ int c_seg_col[31] = {
  18, 20,
  22, 23, 24, 25, 26,
  27, 28, 29, 30, 31,
  40, 41, 42, 43,
  35, 36, 37,
  39,
  32, 33, 34,
  19, 38,
  44, 45, 46, 47, 48, 49
};

struct Params {
  const float* state;
  const float* suit_emb; const float* rank_emb;
  const float *hW1, *hb1, *hW2, *hb2, *hW3, *hb3;
  const float *bW1, *bb1, *bW2, *bb2, *bW3, *bb3;
  const float *cW1, *cb1, *cW2, *cb2, *cW3, *cb3;
  const float *pos_emb, *action_emb, *active_emb, *street_emb, *nump_emb, *blind_emb;
  const float *scalar_W, *scalar_b;
  float* out;
  int nrows;
};

#define CP_COMMIT() asm volatile("cp.async.commit_group;" ::: "memory")
#define CP_WAIT0()  asm volatile("cp.async.wait_group 0;"  ::: "memory")

__device__ __forceinline__ void cp_f(float* dst, const float* __restrict__ src, int n, int tid) {
  for (int e = tid; e < n; e += TPB) dst[e] = src[e];
}

// Async transpose-scatter: W[KC,NN] (row-major global) -> W_T[c*SS + k] in smem.
// Global side coalesced (consecutive tid -> consecutive c); 4B cp.async = issue-cost only.
template<int KC, int NN, int SS>
__device__ __forceinline__ void stageWT(float* WT, const float* __restrict__ W, int tid) {
  unsigned base = (unsigned)__cvta_generic_to_shared(WT);
  for (int e = tid; e < KC * NN; e += TPB) {
    int k = e / NN, c = e - k * NN;
    unsigned dst = base + (unsigned)((c * SS + k) << 2);
    asm volatile("cp.async.ca.shared.global [%0], [%1], 4;" :: "r"(dst), "l"(W + e) : "memory");
  }
}
template<int NN>
__device__ __forceinline__ void stageBv(float* Bb, const float* __restrict__ b, int tid) {
  unsigned base = (unsigned)__cvta_generic_to_shared(Bb);
  for (int e = tid; e < NN; e += TPB) {
    unsigned dst = base + (unsigned)(e << 2);
    asm volatile("cp.async.ca.shared.global [%0], [%1], 4;" :: "r"(dst), "l"(b + e) : "memory");
  }
}

// Y[64,N] = X[64,K] @ W[K,N] + b (store cols < NSTORE), optional leaky.
// Warp tile = 16 rows x 32 cols; lane: rg=lane&3 (rows rt*16 + i*4 + rg),
// cg=lane>>2 (cols ct*32 + j*8 + cg). k-pair f32x2: acc lanes hold even/odd-k
// partial sums, reduced (lo+hi) in epilogue. W is TRANSPOSED in smem with
// slice stride S (=K+2): w2 = LDS.64 of {W[k][c], W[k+1][c]}, bank-distinct.
template<int K, int S, int CTILES, int NSTORE, bool LEAKY>
__device__ __forceinline__ void gemm_tile(const float* __restrict__ Xs, float* __restrict__ Ys,
                                          const float* __restrict__ Wt, const float* __restrict__ Bs,
                                          int tid)
{
  const int wid  = tid >> 5;
  const int lane = tid & 31;
  const int rg   = lane & 3;
  const int cg   = lane >> 2;

  for (int t = wid; t < 4 * CTILES; t += 8) {
    const int rt = t & 3;
    const int ct = t >> 2;
    const float* xb = Xs + (rt * 16 + rg) * XSTR;
    const float* wb = Wt + (ct * 32 + cg) * S;

    ull acc[4][4];
#pragma unroll
    for (int i = 0; i < 4; ++i)
#pragma unroll
      for (int j = 0; j < 4; ++j) acc[i][j] = 0ull;

#pragma unroll 4
    for (int kk = 0; kk < K; kk += 2) {
      ull x2[4], w2[4];
#pragma unroll
      for (int i = 0; i < 4; ++i)
        x2[i] = *reinterpret_cast<const ull*>(xb + i * 4 * XSTR + kk);
#pragma unroll
      for (int j = 0; j < 4; ++j)
        w2[j] = *reinterpret_cast<const ull*>(wb + j * 8 * S + kk);
#pragma unroll
      for (int i = 0; i < 4; ++i)
#pragma unroll
        for (int j = 0; j < 4; ++j)
          asm("fma.rn.f32x2 %0, %1, %2, %3;"
              : "=l"(acc[i][j]) : "l"(w2[j]), "l"(x2[i]), "l"(acc[i][j]));
    }

#pragma unroll
    for (int i = 0; i < 4; ++i) {
      const int r = rt * 16 + i * 4 + rg;
#pragma unroll
      for (int j = 0; j < 4; ++j) {
        const int c = ct * 32 + j * 8 + cg;
        float lo, hi;
        asm("mov.b64 {%0, %1}, %2;" : "=f"(lo), "=f"(hi) : "l"(acc[i][j]));
        float v = lo + hi + Bs[c];
        if (LEAKY) v = fmaxf(v, 0.01f * v);
        if (c < NSTORE) Ys[r * XSTR + c] = v;
      }
    }
  }
}

__global__ void __launch_bounds__(TPB, 1)
PreProcess_kernel(Params p)
{
  extern __shared__ float sm[];
  float* stateS = sm;                         // 64*51  = 3264
  float* X      = stateS + ROWS * SSTR;       // 64*146 = 9344
  float* Y      = X + ROWS * XSTR;            // 9344
  float* WA     = Y + ROWS * XSTR;            // 23360 (covers c1 pad over-read 5*32 x 146)
  float* BA     = WA + 23360;                 // 160
  float* WB     = BA + 160;                   // 9344 (covers board pad over-read 96 x 82)
  float* BB     = WB + 9344;                  // 96
  float* embS   = BB + 96;                    // 528
  // total = 55440 floats = 221760 B

  const int tid  = threadIdx.x;
  const int row0 = blockIdx.x * ROWS;

  // ---- async-stage first weights; meanwhile load state tile + tables ----
  stageWT<64, 64, 66>(WA, p.hW1, tid); stageBv<64>(BA, p.hb1, tid); CP_COMMIT();

  for (int e = tid; e < ROWS * 50; e += TPB) {
    int r = e / 50, c = e - r * 50;
    float v = 0.f;
    if (row0 + r < p.nrows) v = p.state[(size_t)(row0 + r) * 50 + c];
    stateS[r * SSTR + c] = v;
  }
  cp_f(embS + EO_SUIT,   p.suit_emb,   40, tid);
  cp_f(embS + EO_RANK,   p.rank_emb,  112, tid);
  cp_f(embS + EO_POS,    p.pos_emb,    56, tid);
  cp_f(embS + EO_ACTION, p.action_emb, 96, tid);
  cp_f(embS + EO_ACTIVE, p.active_emb, 16, tid);
  cp_f(embS + EO_STREET, p.street_emb, 40, tid);
  cp_f(embS + EO_NUMP,   p.nump_emb,   56, tid);
  cp_f(embS + EO_BLIND,  p.blind_emb,  16, tid);
  cp_f(embS + EO_SW,     p.scalar_W,   48, tid);
  cp_f(embS + EO_SB,     p.scalar_b,   48, tid);
  __syncthreads();

  // ---- build card inputs: X[:,0:64]=hand, X[:,64:144]=board ----
  for (int e = tid; e < ROWS * 144; e += TPB) {
    int r = e / 144, c = e - r * 144;
    int card = c >> 4, t = c & 15;
    float v;
    if (t < 8) {
      int s = (int)stateS[r * SSTR + 2 * card + 1];
      v = embS[EO_SUIT + s * 8 + t];
    } else {
      int rk = (int)stateS[r * SSTR + 2 * card];
      v = embS[EO_RANK + rk * 8 + (t - 8)];
    }
    X[r * XSTR + c] = v;
  }
  CP_WAIT0();
  __syncthreads();

  // ---- 9 layers; stage layer L+1 into the idle W buffer during gemm(L) ----
  stageWT<80, 80, 82>(WB, p.bW1, tid); stageBv<80>(BB, p.bb1, tid); CP_COMMIT();
  gemm_tile<64, 66, 2, 64, true >(X, Y, WA, BA, tid);
  CP_WAIT0(); __syncthreads();

  stageWT<64, 64, 66>(WA, p.hW2, tid); stageBv<64>(BA, p.hb2, tid); CP_COMMIT();
  gemm_tile<80, 82, 3, 80, true >(X + 64, Y + 64, WB, BB, tid);
  CP_WAIT0(); __syncthreads();

  stageWT<80, 80, 82>(WB, p.bW2, tid); stageBv<80>(BB, p.bb2, tid); CP_COMMIT();
  gemm_tile<64, 66, 2, 64, true >(Y, X, WA, BA, tid);
  CP_WAIT0(); __syncthreads();

  stageWT<64, 64, 66>(WA, p.hW3, tid); stageBv<64>(BA, p.hb3, tid); CP_COMMIT();
  gemm_tile<80, 82, 3, 80, true >(Y + 64, X + 64, WB, BB, tid);
  CP_WAIT0(); __syncthreads();

  stageWT<80, 80, 82>(WB, p.bW3, tid); stageBv<80>(BB, p.bb3, tid); CP_COMMIT();
  gemm_tile<64, 66, 2, 64, false>(X, Y, WA, BA, tid);
  CP_WAIT0(); __syncthreads();

  stageWT<144, 144, 146>(WA, p.cW1, tid); stageBv<144>(BA, p.cb1, tid); CP_COMMIT();
  gemm_tile<80, 82, 3, 80, false>(X + 64, Y + 64, WB, BB, tid);
  CP_WAIT0(); __syncthreads();

  stageWT<144, 64, 146>(WB, p.cW2, tid); stageBv<64>(BB, p.cb2, tid); CP_COMMIT();
  gemm_tile<144, 146, 5, 144, true >(Y, X, WA, BA, tid);   // hb L1 (concat = Y[:,0:144])
  CP_WAIT0(); __syncthreads();

  stageWT<64, 64, 66>(WA, p.cW3, tid); stageBv<64>(BA, p.cb3, tid); CP_COMMIT();
  gemm_tile<144, 146, 2, 64, true >(X, Y, WB, BB, tid);
  CP_WAIT0(); __syncthreads();

  gemm_tile<64, 66, 2, 64, false>(Y, X, WA, BA, tid);
  __syncthreads();
  // final hand_board in X[:,0:64]

  // ---- assemble 312-float output rows (coalesced) ----
  size_t obase = (size_t)row0 * 312;
  for (int e = tid; e < ROWS * 312; e += TPB) {
    int r = e / 312, c = e - r * 312;
    if (row0 + r >= p.nrows) continue;
    float v;
    if (c < 64) {
      v = X[r * XSTR + c];
    } else {
      int s = (c - 64) >> 3, j = (c - 64) & 7;
      int base = c_seg_base[s];
      float sv = stateS[r * SSTR + c_seg_col[s]];
      if (base >= 0) {
        int idx = (int)sv;
        v = embS[base + idx * 8 + j];
      } else {
        int w = -base - 1;
        v = fmaf(sv, embS[EO_SW + w * 8 + j], embS[EO_SB + w * 8 + j]);
      }
    }
    p.out[obase + e] = v;
  }
}

extern "C" void kernel_launch(void* const* d_in, const int* in_sizes, int n_in,
                              void* d_out, int out_size)
{
  Params p;
  p.state      = (const float*)d_in[0];
  p.suit_emb   = (const float*)d_in[1];
  p.rank_emb   = (const float*)d_in[2];
  p.hW1 = (const float*)d_in[3];  p.hb1 = (const float*)d_in[4];
  p.hW2 = (const float*)d_in[5];  p.hb2 = (const float*)d_in[6];
  p.hW3 = (const float*)d_in[7];  p.hb3 = (const float*)d_in[8];
  p.bW1 = (const float*)d_in[9];  p.bb1 = (const float*)d_in[10];
  p.bW2 = (const float*)d_in[11]; p.bb2 = (const float*)d_in[12];
  p.bW3 = (const float*)d_in[13]; p.bb3 = (const float*)d_in[14];
  p.cW1 = (const float*)d_in[15]; p.cb1 = (const float*)d_in[16];
  p.cW2 = (const float*)d_in[17]; p.cb2 = (const float*)d_in[18];
  p.cW3 = (const float*)d_in[19]; p.cb3 = (const float*)d_in[20];
  p.pos_emb    = (const float*)d_in[21];
  p.action_emb = (const float*)d_in[22];
  p.active_emb = (const float*)d_in[23];
  p.street_emb = (const float*)d_in[24];
  p.nump_emb   = (const float*)d_in[25];
  p.blind_emb  = (const float*)d_in[26];
  p.scalar_W   = (const float*)d_in[27];
  p.scalar_b   = (const float*)d_in[28];
  p.out   = (float*)d_out;
  p.nrows = in_sizes[0] / 50;

  const int smem_floats = ROWS * SSTR + 2 * ROWS * XSTR
                        + 23360 + 160 + 9344 + 96 + EO_TOTAL;
  const int smem_bytes = smem_floats * (int)sizeof(float);
  cudaFuncSetAttribute(PreProcess_kernel,
                       cudaFuncAttributeMaxDynamicSharedMemorySize, smem_bytes);

  int grid = (p.nrows + ROWS - 1) / ROWS;
  PreProcess_kernel<<<grid, TPB, smem_bytes>>>(p);
}